// round 8
// baseline (speedup 1.0000x reference)
#include <cuda_runtime.h>

// SIR scan, (B,T,F) = (16384, 2048, 2) fp32, 2048 sequential steps per row.
// R6: smem staging fixed the L1 wavefront bound (DRAM 39->62%). R7/R8: deepen
// the cp.async pipeline to a 4-buffer / 3-in-flight ring with ONE __syncthreads
// per chunk, so DRAM latency and LSU issue fully overlap the 2-FFMA carried
// chain. Chunk = 16 steps (128 B/row), padded smem stride 9 float4
// (conflict-free LDS.128), 4 buffers = 36.9 KB static, 2 blocks/SM.
// (R7 bench run was lost to a container failure; identical logic resubmitted.)

#define TT       2048
#define FF       2
#define CHUNK    16                   // timesteps per chunk
#define ROWV4    (CHUNK * FF / 4)     // 8 float4 per row-chunk (128 B)
#define NCH      (TT / CHUNK)         // 128 chunks
#define BDIM     64                   // threads per block = rows per block
#define STR_V4   9                    // padded row stride in float4 (144 B)
#define BUFV4    (BDIM * STR_V4)      // 576 float4 per buffer
#define NBUF     4
#define ROW_STR4 (TT * FF / 4)        // 1024 float4 per global row

#define INV_POP 1e-6f

__device__ __forceinline__ void cp_async16(unsigned smem_addr, const float4* gmem_src) {
    asm volatile("cp.async.cg.shared.global [%0], [%1], 16;\n" :: "r"(smem_addr), "l"(gmem_src));
}
__device__ __forceinline__ void cp_commit() {
    asm volatile("cp.async.commit_group;\n" ::);
}

__device__ __forceinline__ void sir_step(float& S, float& I, float& R,
                                         float beta, float gamma) {
    float bp = beta * INV_POP;           // off-chain
    float a  = bp * S;                   // chain +4
    float Sn = __fmaf_rn(-a, I, S);
    float t  = __fmaf_rn( a, I, I);
    float In = __fmaf_rn(-gamma, I, t);
    R = __fmaf_rn(gamma, I, R);          // off-chain accumulator
    S = Sn;
    I = In;
}

__global__ __launch_bounds__(BDIM, 2)
void sir_scan_kernel(const float* __restrict__ in,     // (B, T, F)
                     const float* __restrict__ init,   // (B, 3)
                     float* __restrict__ out,          // copies x (B, 3)
                     int B, int copies) {
    __shared__ float4 buf[NBUF][BUFV4];                // 4 x 9216 B = 36864 B

    const int tid  = threadIdx.x;
    const int row0 = blockIdx.x * BDIM;
    const int b    = row0 + tid;

    const float4* gin = reinterpret_cast<const float4*>(in);

    float S = 0.f, I = 0.f, R = 0.f;
    if (b < B) {
        S = init[3 * b + 0];
        I = init[3 * b + 1];
        R = init[3 * b + 2];
    }

    // Coalesced staging map: slot s = k*BDIM + tid; 8 consecutive lanes cover
    // one row's 128 B chunk -> warp instruction = 4 rows x 1 line = 4 wavefronts.
    const float4* gbase[ROWV4];   // global base (chunk 0) per k
    unsigned      soff [ROWV4];   // smem byte offset within a buffer per k
#pragma unroll
    for (int k = 0; k < ROWV4; k++) {
        int s   = k * BDIM + tid;
        int row = s >> 3;          // 0..63
        int off = s & 7;           // 0..7
        int gr  = row0 + row;
        if (gr >= B) gr = B - 1;
        gbase[k] = gin + (size_t)gr * ROW_STR4 + off;
        soff[k]  = (unsigned)((row * STR_V4 + off) * sizeof(float4));
    }
    const unsigned sbase = (unsigned)__cvta_generic_to_shared(&buf[0][0]);
    const unsigned bufbytes = (unsigned)(BUFV4 * sizeof(float4));

    // Prologue: fill 3 buffers (chunks 0,1,2)
#pragma unroll
    for (int p = 0; p < 3; p++) {
        unsigned sb = sbase + (unsigned)p * bufbytes;
#pragma unroll
        for (int k = 0; k < ROWV4; k++)
            cp_async16(sb + soff[k], gbase[k] + (size_t)p * ROWV4);
        cp_commit();
    }

#pragma unroll 1
    for (int c = 0; c < NCH; c++) {
        // ensure chunk c has landed (keep newest <=2 groups in flight)
        int rem = NCH - 1 - c;
        if (rem >= 2)      asm volatile("cp.async.wait_group 2;\n" ::);
        else if (rem == 1) asm volatile("cp.async.wait_group 1;\n" ::);
        else               asm volatile("cp.async.wait_group 0;\n" ::);
        __syncthreads();   // publishes chunk c AND proves consume of c-1 done
                           // -> slot (c+3)%4 (==(c-1)%4) is free to refill

        if (c + 3 < NCH) {
            unsigned sb = sbase + (unsigned)((c + 3) & (NBUF - 1)) * bufbytes;
#pragma unroll
            for (int k = 0; k < ROWV4; k++)
                cp_async16(sb + soff[k], gbase[k] + (size_t)(c + 3) * ROWV4);
            cp_commit();
        }

        // consume chunk c: own padded smem row, conflict-free LDS.128
        const float4* cb = &buf[c & (NBUF - 1)][tid * STR_V4];
#pragma unroll
        for (int j = 0; j < ROWV4; j++) {
            float4 u = cb[j];
            sir_step(S, I, R, u.x, u.y);
            sir_step(S, I, R, u.z, u.w);
        }
    }

    if (b < B) {
        for (int k = 0; k < copies; k++) {
            float* o = out + (size_t)k * (size_t)B * 3 + 3 * b;
            o[0] = S;
            o[1] = I;
            o[2] = R;
        }
    }
}

extern "C" void kernel_launch(void* const* d_in, const int* in_sizes, int n_in,
                              void* d_out, int out_size) {
    const float* in   = (const float*)d_in[0];   // inputs (B,T,F) fp32
    const float* init = (const float*)d_in[1];   // initial_state (B,3) fp32
    float* out = (float*)d_out;

    int B = in_sizes[1] / 3;
    int copies = out_size / (B * 3);
    if (copies < 1) copies = 1;

    int blocks = (B + BDIM - 1) / BDIM;          // 256 blocks of 64 threads
    sir_scan_kernel<<<blocks, BDIM>>>(in, init, out, B, copies);
}

// round 9
// speedup vs baseline: 1.1127x; 1.1127x over previous
#include <cuda_runtime.h>

// SIR scan, (B,T,F) = (16384, 2048, 2) fp32, 2048 sequential steps per row.
// R8 post-mortem: smaller chunks kept in-flight bytes constant but doubled
// barrier/wait overhead -> regression. R9: 32-step chunks, 3 buffers
// (34.8 KB/block in flight via wait_group 2), and WARP-PRIVATE pipelines:
// each warp stages+consumes its own 32 rows, so the per-chunk sync is a
// __syncwarp (no __syncthreads anywhere in the loop). 52.2 KB dynamic smem,
// 2 blocks/SM.

#define TT       2048
#define FF       2
#define CHUNK    32                    // timesteps per chunk
#define ROWV4    (CHUNK * FF / 4)      // 16 float4 per row-chunk (256 B)
#define NCH      (TT / CHUNK)          // 64 chunks
#define BDIM     64                    // 2 warps; 32 rows per warp
#define WROWS    32
#define STR_V4   17                    // padded row stride (68 floats): conflict-free LDS.128
#define WBUFV4   (WROWS * STR_V4)      // 544 float4 per warp-buffer
#define NBUF     3
#define SMEM_BYTES (2 * NBUF * WBUFV4 * 16)   // 52224
#define ROW_STR4 (TT * FF / 4)         // 1024 float4 per global row

#define INV_POP 1e-6f

__device__ __forceinline__ void cp_async16(unsigned smem_addr, const float4* gmem_src) {
    asm volatile("cp.async.cg.shared.global [%0], [%1], 16;\n" :: "r"(smem_addr), "l"(gmem_src));
}
__device__ __forceinline__ void cp_commit() {
    asm volatile("cp.async.commit_group;\n" ::);
}

__device__ __forceinline__ void sir_step(float& S, float& I, float& R,
                                         float beta, float gamma) {
    float bp = beta * INV_POP;           // off-chain
    float a  = bp * S;                   // chain +4
    float Sn = __fmaf_rn(-a, I, S);
    float t  = __fmaf_rn( a, I, I);
    float In = __fmaf_rn(-gamma, I, t);
    R = __fmaf_rn(gamma, I, R);          // off-chain accumulator
    S = Sn;
    I = In;
}

__global__ __launch_bounds__(BDIM, 2)
void sir_scan_kernel(const float* __restrict__ in,     // (B, T, F)
                     const float* __restrict__ init,   // (B, 3)
                     float* __restrict__ out,          // copies x (B, 3)
                     int B, int copies) {
    extern __shared__ float4 smem[];   // [2 warps][NBUF][WBUFV4]

    const int tid  = threadIdx.x;
    const int lane = tid & 31;
    const int w    = tid >> 5;
    const int row0 = blockIdx.x * BDIM;
    const int b    = row0 + tid;       // this thread's batch row (consume side)

    const float4* gin = reinterpret_cast<const float4*>(in);

    float S = 0.f, I = 0.f, R = 0.f;
    if (b < B) {
        S = init[3 * b + 0];
        I = init[3 * b + 1];
        R = init[3 * b + 2];
    }

    // Warp-private staging map: slot s = k*32 + lane; 16 consecutive lanes
    // cover one row's 256 B chunk -> warp load = 2 rows x 2 lines = 4 wf.
    const float4* gbase[ROWV4];
    unsigned      soff [ROWV4];
#pragma unroll
    for (int k = 0; k < ROWV4; k++) {
        int s   = k * WROWS + lane;
        int row = s >> 4;              // 0..31 (warp-local)
        int off = s & 15;              // 0..15
        int gr  = row0 + w * WROWS + row;
        if (gr >= B) gr = B - 1;
        gbase[k] = gin + (size_t)gr * ROW_STR4 + off;
        soff[k]  = (unsigned)((row * STR_V4 + off) * sizeof(float4));
    }
    // warp w's buffer p base (bytes in shared window)
    const unsigned wbase = (unsigned)__cvta_generic_to_shared(smem)
                         + (unsigned)(w * NBUF * WBUFV4 * sizeof(float4));
    const unsigned bufbytes = (unsigned)(WBUFV4 * sizeof(float4));
    const float4*  wbuf = smem + w * NBUF * WBUFV4;

    // Prologue: fill 3 warp-buffers (chunks 0,1,2)
#pragma unroll
    for (int p = 0; p < NBUF; p++) {
        unsigned sb = wbase + (unsigned)p * bufbytes;
#pragma unroll
        for (int k = 0; k < ROWV4; k++)
            cp_async16(sb + soff[k], gbase[k] + (size_t)p * ROWV4);
        cp_commit();
    }

    int slot = 0;                      // slot of chunk c (c mod 3, tracked)
#pragma unroll 1
    for (int c = 0; c < NCH - 2; c++) {
        asm volatile("cp.async.wait_group 2;\n" ::);   // chunk c landed
        __syncwarp();                                  // all lanes' groups landed;
                                                       // also proves c-1 consumed
        // refill slot of c-1 (== slot of c+2) with chunk c+2... c+2 already
        // issued in prologue for c<1; steady state: issue chunk c+3? No:
        // invariant: before this iter, chunks c..c+2 are issued. Issue c+3 now
        // into the slot freed by c-1 IS c+3 mod 3 == (c-1) mod 3? c+3 ≡ c (mod 3).
        // Correct scheme: issue chunk c+3 AFTER consuming c (slot reused next iter).
        // Simpler + safe: issue c+3 here only when c >= 1 is not needed because
        // slot(c+3)=slot(c) which is being consumed THIS iteration. So issue
        // c+3 after the consume loop below.

        const float4* cb = wbuf + slot * WBUFV4 + lane * STR_V4;
#pragma unroll
        for (int j = 0; j < ROWV4; j++) {
            float4 u = cb[j];
            sir_step(S, I, R, u.x, u.y);
            sir_step(S, I, R, u.z, u.w);
        }
        __syncwarp();                  // warp done with slot(c) -> refill it
        if (c + 3 < NCH) {
            unsigned sb = wbase + (unsigned)slot * bufbytes;
#pragma unroll
            for (int k = 0; k < ROWV4; k++)
                cp_async16(sb + soff[k], gbase[k] + (size_t)(c + 3) * ROWV4);
            cp_commit();
        }
        slot = (slot == NBUF - 1) ? 0 : slot + 1;
    }

    // Epilogue: chunks NCH-2 and NCH-1 (no further issues outstanding beyond them)
    {
        asm volatile("cp.async.wait_group 1;\n" ::);
        __syncwarp();
        const float4* cb = wbuf + slot * WBUFV4 + lane * STR_V4;
#pragma unroll
        for (int j = 0; j < ROWV4; j++) {
            float4 u = cb[j];
            sir_step(S, I, R, u.x, u.y);
            sir_step(S, I, R, u.z, u.w);
        }
        slot = (slot == NBUF - 1) ? 0 : slot + 1;

        asm volatile("cp.async.wait_group 0;\n" ::);
        __syncwarp();
        const float4* cb2 = wbuf + slot * WBUFV4 + lane * STR_V4;
#pragma unroll
        for (int j = 0; j < ROWV4; j++) {
            float4 u = cb2[j];
            sir_step(S, I, R, u.x, u.y);
            sir_step(S, I, R, u.z, u.w);
        }
    }

    if (b < B) {
        for (int k = 0; k < copies; k++) {
            float* o = out + (size_t)k * (size_t)B * 3 + 3 * b;
            o[0] = S;
            o[1] = I;
            o[2] = R;
        }
    }
}

extern "C" void kernel_launch(void* const* d_in, const int* in_sizes, int n_in,
                              void* d_out, int out_size) {
    const float* in   = (const float*)d_in[0];   // inputs (B,T,F) fp32
    const float* init = (const float*)d_in[1];   // initial_state (B,3) fp32
    float* out = (float*)d_out;

    int B = in_sizes[1] / 3;
    int copies = out_size / (B * 3);
    if (copies < 1) copies = 1;

    cudaFuncSetAttribute(sir_scan_kernel,
                         cudaFuncAttributeMaxDynamicSharedMemorySize, SMEM_BYTES);

    int blocks = (B + BDIM - 1) / BDIM;          // 256 blocks of 64 threads
    sir_scan_kernel<<<blocks, BDIM, SMEM_BYTES>>>(in, init, out, B, copies);
}

// round 11
// speedup vs baseline: 1.1154x; 1.0024x over previous
#include <cuda_runtime.h>

// SIR scan, (B,T,F) = (16384, 2048, 2) fp32, 2048 sequential steps per row.
// R9 post-mortem: DRAM stuck ~63-65% regardless of pipeline depth. R10/R11:
// (a) per-SM load imbalance: 16-row / 1-warp blocks (1024 blocks, <=7/SM,
//     max SM load 1.75 MB ~= ideal vs 2 MB before), and
// (b) DRAM activation granularity: CHUNK=64 -> 512 B contiguous per row per
//     access (half the row-activation overhead of 256 B chunks).
// Warp-private 3-buffer cp.async ring, __syncwarp-only. Lanes 0-15 own one
// recurrence row each; all 32 lanes stage. Padded stride 33*float4 keeps
// LDS.128 conflict-free. (R10 run lost to container failure; resubmitted.)

#define TT       2048
#define FF       2
#define CHUNK    64                    // timesteps per chunk
#define ROWV4    (CHUNK * FF / 4)      // 32 float4 per row-chunk (512 B)
#define NCH      (TT / CHUNK)          // 32 chunks
#define BDIM     32                    // 1 warp per block
#define WROWS    16                    // rows per block/warp
#define STR_V4   33                    // padded row stride in float4 (528 B)
#define WBUFV4   (WROWS * STR_V4)      // 528 float4 per buffer
#define NBUF     3
#define SMEM_BYTES (NBUF * WBUFV4 * 16)   // 25344 B per block
#define ROW_STR4 (TT * FF / 4)         // 1024 float4 per global row

#define INV_POP 1e-6f

__device__ __forceinline__ void cp_async16(unsigned smem_addr, const float4* gmem_src) {
    asm volatile("cp.async.cg.shared.global [%0], [%1], 16;\n" :: "r"(smem_addr), "l"(gmem_src));
}
__device__ __forceinline__ void cp_commit() {
    asm volatile("cp.async.commit_group;\n" ::);
}

__device__ __forceinline__ void sir_step(float& S, float& I, float& R,
                                         float beta, float gamma) {
    float bp = beta * INV_POP;           // off-chain
    float a  = bp * S;                   // chain +4
    float Sn = __fmaf_rn(-a, I, S);
    float t  = __fmaf_rn( a, I, I);
    float In = __fmaf_rn(-gamma, I, t);
    R = __fmaf_rn(gamma, I, R);          // off-chain accumulator
    S = Sn;
    I = In;
}

__global__ __launch_bounds__(BDIM, 7)
void sir_scan_kernel(const float* __restrict__ in,     // (B, T, F)
                     const float* __restrict__ init,   // (B, 3)
                     float* __restrict__ out,          // copies x (B, 3)
                     int B, int copies) {
    extern __shared__ float4 smem[];   // [NBUF][WBUFV4]

    const int lane = threadIdx.x;      // 0..31
    const int row0 = blockIdx.x * WROWS;
    const int b    = row0 + lane;      // valid recurrence row for lane < WROWS

    const float4* gin = reinterpret_cast<const float4*>(in);

    float S = 0.f, I = 0.f, R = 0.f;
    if (lane < WROWS && b < B) {
        S = init[3 * b + 0];
        I = init[3 * b + 1];
        R = init[3 * b + 2];
    }

    // Staging map: warp-load k covers row k's full 512 B chunk.
    //   gmem: row (row0+k), float4 index = c*ROWV4 + lane
    //   smem: buffer slot, float4 index = k*STR_V4 + lane
    const float4* gbase[WROWS];
    unsigned      soff [WROWS];
#pragma unroll
    for (int k = 0; k < WROWS; k++) {
        int gr = row0 + k;
        if (gr >= B) gr = B - 1;
        gbase[k] = gin + (size_t)gr * ROW_STR4 + lane;
        soff[k]  = (unsigned)((k * STR_V4 + lane) * sizeof(float4));
    }
    const unsigned sbase = (unsigned)__cvta_generic_to_shared(smem);
    const unsigned bufbytes = (unsigned)(WBUFV4 * sizeof(float4));

    // Prologue: fill 3 buffers (chunks 0,1,2)
#pragma unroll
    for (int p = 0; p < NBUF; p++) {
        unsigned sb = sbase + (unsigned)p * bufbytes;
#pragma unroll
        for (int k = 0; k < WROWS; k++)
            cp_async16(sb + soff[k], gbase[k] + (size_t)p * ROWV4);
        cp_commit();
    }

    int slot = 0;
#pragma unroll 1
    for (int c = 0; c < NCH - 2; c++) {
        asm volatile("cp.async.wait_group 2;\n" ::);   // chunk c landed
        __syncwarp();

        // consume chunk c: lane < WROWS reads its own padded smem row
        if (lane < WROWS) {
            const float4* cb = smem + slot * WBUFV4 + lane * STR_V4;
#pragma unroll
            for (int j = 0; j < ROWV4; j++) {
                float4 u = cb[j];
                sir_step(S, I, R, u.x, u.y);
                sir_step(S, I, R, u.z, u.w);
            }
        }
        __syncwarp();                  // consume done -> refill slot with chunk c+3
        if (c + 3 < NCH) {
            unsigned sb = sbase + (unsigned)slot * bufbytes;
#pragma unroll
            for (int k = 0; k < WROWS; k++)
                cp_async16(sb + soff[k], gbase[k] + (size_t)(c + 3) * ROWV4);
            cp_commit();
        }
        slot = (slot == NBUF - 1) ? 0 : slot + 1;
    }

    // Epilogue: chunks NCH-2, NCH-1
    {
        asm volatile("cp.async.wait_group 1;\n" ::);
        __syncwarp();
        if (lane < WROWS) {
            const float4* cb = smem + slot * WBUFV4 + lane * STR_V4;
#pragma unroll
            for (int j = 0; j < ROWV4; j++) {
                float4 u = cb[j];
                sir_step(S, I, R, u.x, u.y);
                sir_step(S, I, R, u.z, u.w);
            }
        }
        slot = (slot == NBUF - 1) ? 0 : slot + 1;

        asm volatile("cp.async.wait_group 0;\n" ::);
        __syncwarp();
        if (lane < WROWS) {
            const float4* cb = smem + slot * WBUFV4 + lane * STR_V4;
#pragma unroll
            for (int j = 0; j < ROWV4; j++) {
                float4 u = cb[j];
                sir_step(S, I, R, u.x, u.y);
                sir_step(S, I, R, u.z, u.w);
            }
        }
    }

    if (lane < WROWS && b < B) {
        for (int k = 0; k < copies; k++) {
            float* o = out + (size_t)k * (size_t)B * 3 + 3 * b;
            o[0] = S;
            o[1] = I;
            o[2] = R;
        }
    }
}

extern "C" void kernel_launch(void* const* d_in, const int* in_sizes, int n_in,
                              void* d_out, int out_size) {
    const float* in   = (const float*)d_in[0];   // inputs (B,T,F) fp32
    const float* init = (const float*)d_in[1];   // initial_state (B,3) fp32
    float* out = (float*)d_out;

    int B = in_sizes[1] / 3;
    int copies = out_size / (B * 3);
    if (copies < 1) copies = 1;

    cudaFuncSetAttribute(sir_scan_kernel,
                         cudaFuncAttributeMaxDynamicSharedMemorySize, SMEM_BYTES);

    int blocks = (B + WROWS - 1) / WROWS;        // 1024 blocks of 1 warp
    sir_scan_kernel<<<blocks, BDIM, SMEM_BYTES>>>(in, init, out, B, copies);
}

// round 12
// speedup vs baseline: 1.1167x; 1.0012x over previous
#include <cuda_runtime.h>

// SIR scan, (B,T,F) = (16384, 2048, 2) fp32, 2048 sequential steps per row.
// R11 post-mortem: DRAM pinned at 63.4% across totally different schedules ->
// binder is per-warp issue/serialization, not a pipe. R12: (1) all 32 lanes
// own a row (halves FMA warp-instructions per row), (2) 5-op step using exact
// SIR conservation (R_final = S0+I0+R0 - S - I; no per-step R accumulator),
// (3) warp-private 3-buffer cp.async ring (CHUNK=32), __syncwarp only,
// 512 one-warp blocks, ~4 blocks/SM.

#define TT       2048
#define FF       2
#define CHUNK    32                    // timesteps per chunk
#define ROWV4    (CHUNK * FF / 4)      // 16 float4 per row-chunk (256 B)
#define NCH      (TT / CHUNK)          // 64 chunks
#define BDIM     32                    // 1 warp per block
#define WROWS    32                    // rows per block/warp (all lanes active)
#define STR_V4   17                    // padded row stride in float4 (272 B)
#define WBUFV4   (WROWS * STR_V4)      // 544 float4 per buffer
#define NBUF     3
#define SMEM_BYTES (NBUF * WBUFV4 * 16)   // 26112 B per block
#define ROW_STR4 (TT * FF / 4)         // 1024 float4 per global row

#define INV_POP 1e-6f

__device__ __forceinline__ void cp_async16(unsigned smem_addr, const float4* gmem_src) {
    asm volatile("cp.async.cg.shared.global [%0], [%1], 16;\n" :: "r"(smem_addr), "l"(gmem_src));
}
__device__ __forceinline__ void cp_commit() {
    asm volatile("cp.async.commit_group;\n" ::);
}

// 5-op SIR step. R is recovered at the end via exact conservation.
__device__ __forceinline__ void sir_step(float& S, float& I,
                                         float beta, float gamma) {
    float bp = beta * INV_POP;           // off-chain (data only)
    float a  = bp * S;                   // chain
    float d  = a - gamma;                // chain
    float Sn = __fmaf_rn(-a, I, S);      // S - new_inf
    float In = __fmaf_rn( d, I, I);      // I + (a - gamma)*I
    S = Sn;
    I = In;
}

__global__ __launch_bounds__(BDIM, 4)
void sir_scan_kernel(const float* __restrict__ in,     // (B, T, F)
                     const float* __restrict__ init,   // (B, 3)
                     float* __restrict__ out,          // copies x (B, 3)
                     int B, int copies) {
    extern __shared__ float4 smem[];   // [NBUF][WBUFV4]

    const int lane = threadIdx.x;      // 0..31
    const int row0 = blockIdx.x * WROWS;
    const int b    = row0 + lane;

    const float4* gin = reinterpret_cast<const float4*>(in);

    float S = 0.f, I = 0.f, total = 0.f;
    if (b < B) {
        S = init[3 * b + 0];
        I = init[3 * b + 1];
        float R0 = init[3 * b + 2];
        total = S + I + R0;            // conserved quantity
    }

    // Staging map: slot s = k*32 + lane; 16 consecutive lanes cover one row's
    // 256 B chunk -> each warp cp.async = 2 rows x 2 lines = 4 wavefronts.
    const float4* gbase[ROWV4];        // ROWV4 == 16 staging instructions
    unsigned      soff [ROWV4];
#pragma unroll
    for (int k = 0; k < ROWV4; k++) {
        int s   = k * WROWS + lane;
        int row = s >> 4;              // 0..31
        int off = s & 15;              // 0..15
        int gr  = row0 + row;
        if (gr >= B) gr = B - 1;
        gbase[k] = gin + (size_t)gr * ROW_STR4 + off;
        soff[k]  = (unsigned)((row * STR_V4 + off) * sizeof(float4));
    }
    const unsigned sbase    = (unsigned)__cvta_generic_to_shared(smem);
    const unsigned bufbytes = (unsigned)(WBUFV4 * sizeof(float4));

    // Prologue: fill 3 buffers (chunks 0,1,2)
#pragma unroll
    for (int p = 0; p < NBUF; p++) {
        unsigned sb = sbase + (unsigned)p * bufbytes;
#pragma unroll
        for (int k = 0; k < ROWV4; k++)
            cp_async16(sb + soff[k], gbase[k] + (size_t)p * ROWV4);
        cp_commit();
    }

    int slot = 0;
#pragma unroll 1
    for (int c = 0; c < NCH - 2; c++) {
        asm volatile("cp.async.wait_group 2;\n" ::);   // chunk c landed
        __syncwarp();

        // consume chunk c: every lane reads its own padded smem row
        {
            const float4* cb = smem + slot * WBUFV4 + lane * STR_V4;
#pragma unroll
            for (int j = 0; j < ROWV4; j++) {
                float4 u = cb[j];
                sir_step(S, I, u.x, u.y);
                sir_step(S, I, u.z, u.w);
            }
        }
        __syncwarp();                  // consume done -> refill slot with chunk c+3
        if (c + 3 < NCH) {
            unsigned sb = sbase + (unsigned)slot * bufbytes;
#pragma unroll
            for (int k = 0; k < ROWV4; k++)
                cp_async16(sb + soff[k], gbase[k] + (size_t)(c + 3) * ROWV4);
            cp_commit();
        }
        slot = (slot == NBUF - 1) ? 0 : slot + 1;
    }

    // Epilogue: chunks NCH-2, NCH-1
    {
        asm volatile("cp.async.wait_group 1;\n" ::);
        __syncwarp();
        const float4* cb = smem + slot * WBUFV4 + lane * STR_V4;
#pragma unroll
        for (int j = 0; j < ROWV4; j++) {
            float4 u = cb[j];
            sir_step(S, I, u.x, u.y);
            sir_step(S, I, u.z, u.w);
        }
        slot = (slot == NBUF - 1) ? 0 : slot + 1;

        asm volatile("cp.async.wait_group 0;\n" ::);
        __syncwarp();
        const float4* cb2 = smem + slot * WBUFV4 + lane * STR_V4;
#pragma unroll
        for (int j = 0; j < ROWV4; j++) {
            float4 u = cb2[j];
            sir_step(S, I, u.x, u.y);
            sir_step(S, I, u.z, u.w);
        }
    }

    if (b < B) {
        float R = (total - S) - I;     // exact conservation
        for (int k = 0; k < copies; k++) {
            float* o = out + (size_t)k * (size_t)B * 3 + 3 * b;
            o[0] = S;
            o[1] = I;
            o[2] = R;
        }
    }
}

extern "C" void kernel_launch(void* const* d_in, const int* in_sizes, int n_in,
                              void* d_out, int out_size) {
    const float* in   = (const float*)d_in[0];   // inputs (B,T,F) fp32
    const float* init = (const float*)d_in[1];   // initial_state (B,3) fp32
    float* out = (float*)d_out;

    int B = in_sizes[1] / 3;
    int copies = out_size / (B * 3);
    if (copies < 1) copies = 1;

    cudaFuncSetAttribute(sir_scan_kernel,
                         cudaFuncAttributeMaxDynamicSharedMemorySize, SMEM_BYTES);

    int blocks = (B + WROWS - 1) / WROWS;        // 512 blocks of 1 warp
    sir_scan_kernel<<<blocks, BDIM, SMEM_BYTES>>>(in, init, out, B, copies);
}